// round 2
// baseline (speedup 1.0000x reference)
#include <cuda_runtime.h>
#include <math.h>

#define BB   2
#define TT   1024
#define HH   1024
#define NHD  16
#define NKVH 4
#define HDD  64
#define NE   64
#define TOPK 8
#define NI   512
#define NTOK (BB*TT)   // 2048

// ---------------- scratch (device globals; no runtime allocation) ----------
__device__ float g_h  [NTOK*HH];        // rmsnorm1 output
__device__ float g_q  [NTOK*NHD*HDD];
__device__ float g_k  [NTOK*NKVH*HDD];
__device__ float g_v  [NTOK*NKVH*HDD];
__device__ float g_att[NTOK*NHD*HDD];
__device__ float g_f  [NTOK*HH];        // rmsnorm2 output
__device__ int   g_cnt[NE];
__device__ int   g_tok[NE*NTOK];
__device__ float g_scr[NE*NTOK];

// ---------------- rmsnorm ----------------
__global__ void rmsnorm_k(const float* __restrict__ x, const float* __restrict__ w,
                          float* __restrict__ o) {
    int row = blockIdx.x;
    const float* xr = x + (size_t)row * HH;
    float ss = 0.f;
    for (int i = threadIdx.x; i < HH; i += 256) { float v = xr[i]; ss += v * v; }
    __shared__ float red[256];
    red[threadIdx.x] = ss; __syncthreads();
    for (int s = 128; s > 0; s >>= 1) {
        if (threadIdx.x < s) red[threadIdx.x] += red[threadIdx.x + s];
        __syncthreads();
    }
    float inv = rsqrtf(red[0] * (1.0f / HH) + 1e-6f);
    float* op = o + (size_t)row * HH;
    for (int i = threadIdx.x; i < HH; i += 256) op[i] = xr[i] * inv * w[i];
}

// ---------------- tiled SGEMM: C[M,N] = A[M,K] @ B[K,N] (+R) ----------------
// BM=BN=64, BK=16, 256 threads, 4x4 per thread. M,N mult of 64; K mult of 16.
__global__ __launch_bounds__(256)
void sgemm_k(const float* __restrict__ A, const float* __restrict__ B,
             const float* __restrict__ R, float* __restrict__ C,
             int M, int N, int K) {
    __shared__ float As[16][64];
    __shared__ float Bs[16][64];
    int tid = threadIdx.x;
    int tx = tid & 15, ty = tid >> 4;
    const float* Ab = A + (size_t)blockIdx.y * 64 * K;
    const float* Bb = B + (size_t)blockIdx.x * 64;
    float acc[4][4];
    #pragma unroll
    for (int i = 0; i < 4; i++)
        #pragma unroll
        for (int j = 0; j < 4; j++) acc[i][j] = 0.f;

    for (int k0 = 0; k0 < K; k0 += 16) {
        #pragma unroll
        for (int l = 0; l < 4; l++) {
            int idx = tid + l * 256;          // 0..1023
            int m = idx >> 4, k = idx & 15;
            As[k][m] = Ab[(size_t)m * K + k0 + k];
        }
        #pragma unroll
        for (int l = 0; l < 4; l++) {
            int idx = tid + l * 256;
            int k = idx >> 6, n = idx & 63;
            Bs[k][n] = Bb[(size_t)(k0 + k) * N + n];
        }
        __syncthreads();
        #pragma unroll
        for (int k = 0; k < 16; k++) {
            float a[4], b[4];
            #pragma unroll
            for (int i = 0; i < 4; i++) a[i] = As[k][ty * 4 + i];
            #pragma unroll
            for (int j = 0; j < 4; j++) b[j] = Bs[k][tx * 4 + j];
            #pragma unroll
            for (int i = 0; i < 4; i++)
                #pragma unroll
                for (int j = 0; j < 4; j++) acc[i][j] += a[i] * b[j];
        }
        __syncthreads();
    }
    #pragma unroll
    for (int i = 0; i < 4; i++) {
        int m = blockIdx.y * 64 + ty * 4 + i;
        #pragma unroll
        for (int j = 0; j < 4; j++) {
            int n = blockIdx.x * 64 + tx * 4 + j;
            float v = acc[i][j];
            if (R) v += R[(size_t)m * N + n];
            C[(size_t)m * N + n] = v;
        }
    }
}

// ---------------- RoPE (in-place), heads = NHD or NKVH ----------------
__global__ void rope_k(float* __restrict__ q, const float* __restrict__ cosp,
                       const float* __restrict__ sinp, int heads, int total) {
    int idx = blockIdx.x * blockDim.x + threadIdx.x;
    if (idx >= total) return;
    int d  = idx & 31;
    int t2 = idx >> 5;
    int hh = t2 % heads;
    int n  = t2 / heads;
    int t  = n & (TT - 1);
    float* p = q + ((size_t)n * heads + hh) * HDD;
    float c1 = cosp[t * HDD + d],      s1 = sinp[t * HDD + d];
    float c2 = cosp[t * HDD + d + 32], s2 = sinp[t * HDD + d + 32];
    float a = p[d], b = p[d + 32];
    p[d]      = a * c1 - b * s1;
    p[d + 32] = b * c2 + a * s2;
}

// ---------------- causal GQA attention (online softmax) ----------------
// grid: (TT/128, BB*NHD), block 128; one thread per query row.
__global__ __launch_bounds__(128)
void attn_k(const float* __restrict__ q, const float* __restrict__ k,
            const float* __restrict__ v, float* __restrict__ o) {
    __shared__ float Ks[64][HDD];
    __shared__ float Vs[64][HDD];
    int bh  = blockIdx.y;
    int b   = bh / NHD;
    int h   = bh % NHD;
    int kvh = h / (NHD / NKVH);
    int qi  = blockIdx.x * 128 + threadIdx.x;

    float qr[HDD], orr[HDD];
    const float* qp = q + (((size_t)(b * TT + qi)) * NHD + h) * HDD;
    #pragma unroll
    for (int d = 0; d < HDD; d++) { qr[d] = qp[d] * 0.125f; orr[d] = 0.f; }
    float m = -1e30f, l = 0.f;

    int qmax = blockIdx.x * 128 + 127;
    for (int j0 = 0; j0 <= qmax; j0 += 64) {
        __syncthreads();
        for (int e = threadIdx.x; e < 64 * (HDD / 4); e += 128) {
            int jj = e >> 4;
            int dd = (e & 15) * 4;
            size_t base = (((size_t)(b * TT + j0 + jj)) * NKVH + kvh) * HDD + dd;
            *(float4*)&Ks[jj][dd] = *(const float4*)(k + base);
            *(float4*)&Vs[jj][dd] = *(const float4*)(v + base);
        }
        __syncthreads();
        int jend = qi - j0 + 1;
        if (jend > 64) jend = 64;
        for (int jj = 0; jj < jend; jj++) {
            float s = 0.f;
            #pragma unroll
            for (int d = 0; d < HDD; d++) s += qr[d] * Ks[jj][d];
            if (s > m) {
                float f = __expf(m - s);
                l *= f;
                #pragma unroll
                for (int d = 0; d < HDD; d++) orr[d] *= f;
                m = s;
            }
            float p = __expf(s - m);
            l += p;
            #pragma unroll
            for (int d = 0; d < HDD; d++) orr[d] += p * Vs[jj][d];
        }
    }
    float invl = 1.f / l;
    float* op = o + (((size_t)(b * TT + qi)) * NHD + h) * HDD;
    #pragma unroll
    for (int d = 0; d < HDD; d++) op[d] = orr[d] * invl;
}

// ---------------- router top-8 select + expert scatter ----------------
__global__ void zero_cnt_k() {
    if (threadIdx.x < NE) g_cnt[threadIdx.x] = 0;
}

__global__ void topk_k(const float* __restrict__ logits) {
    int n = blockIdx.x * blockDim.x + threadIdx.x;
    if (n >= NTOK) return;
    float lg[NE];
    for (int e = 0; e < NE; e++) lg[e] = logits[(size_t)n * NE + e];
    int   ids[TOPK];
    float vals[TOPK];
    for (int kk = 0; kk < TOPK; kk++) {
        int best = 0; float bv = lg[0];
        for (int e = 1; e < NE; e++) if (lg[e] > bv) { bv = lg[e]; best = e; }
        ids[kk] = best; vals[kk] = bv; lg[best] = -1e30f;
    }
    // renormalized top-k of full softmax == softmax over top-8 logits (exact)
    float mx = vals[0], sum = 0.f;
    for (int kk = 0; kk < TOPK; kk++) { vals[kk] = __expf(vals[kk] - mx); sum += vals[kk]; }
    float inv = 1.f / sum;
    for (int kk = 0; kk < TOPK; kk++) {
        int e = ids[kk];
        int p = atomicAdd(&g_cnt[e], 1);
        g_tok[e * NTOK + p] = n;
        g_scr[e * NTOK + p] = vals[kk] * inv;
    }
}

// ---------------- grouped MoE: per (expert, 16-token tile) ----------------
__global__ __launch_bounds__(256)
void moe_k(const float* __restrict__ f, const float* __restrict__ Wg,
           const float* __restrict__ Wu, const float* __restrict__ Wd,
           float* __restrict__ out) {
    int e    = blockIdx.x;
    int tile = blockIdx.y;
    int nt   = g_cnt[e];
    int t0   = tile * 16;
    if (t0 >= nt) return;

    __shared__ float Fs[16][64];
    __shared__ float Gs[16][NI];
    __shared__ int   toks[16];
    __shared__ float scs[16];
    int tid = threadIdx.x;
    if (tid < 16) {
        int ti = t0 + tid;
        toks[tid] = (ti < nt) ? g_tok[e * NTOK + ti] : -1;
        scs[tid]  = (ti < nt) ? g_scr[e * NTOK + ti] : 0.f;
    }
    __syncthreads();

    // gate/up: thread owns intermediate cols (2*tid, 2*tid+1) for all 16 tokens
    float2 ag[16], au[16];
    #pragma unroll
    for (int t = 0; t < 16; t++) { ag[t] = make_float2(0.f, 0.f); au[t] = make_float2(0.f, 0.f); }

    const float* Wge = Wg + (size_t)e * HH * NI;
    const float* Wue = Wu + (size_t)e * HH * NI;

    for (int h0 = 0; h0 < HH; h0 += 64) {
        __syncthreads();
        #pragma unroll
        for (int lI = 0; lI < 4; lI++) {
            int idx = tid + lI * 256;
            int row = idx >> 6, col = idx & 63;
            int tk = toks[row];
            Fs[row][col] = (tk >= 0) ? f[(size_t)tk * HH + h0 + col] : 0.f;
        }
        __syncthreads();
        #pragma unroll 4
        for (int hh = 0; hh < 64; hh++) {
            float2 wg = *(const float2*)(Wge + (size_t)(h0 + hh) * NI + tid * 2);
            float2 wu = *(const float2*)(Wue + (size_t)(h0 + hh) * NI + tid * 2);
            #pragma unroll
            for (int t = 0; t < 16; t++) {
                float fv = Fs[t][hh];
                ag[t].x += fv * wg.x; ag[t].y += fv * wg.y;
                au[t].x += fv * wu.x; au[t].y += fv * wu.y;
            }
        }
    }
    __syncthreads();
    #pragma unroll
    for (int t = 0; t < 16; t++) {
        float gx = ag[t].x, gy = ag[t].y;
        float sx = gx / (1.f + __expf(-gx));
        float sy = gy / (1.f + __expf(-gy));
        Gs[t][tid * 2]     = sx * au[t].x;
        Gs[t][tid * 2 + 1] = sy * au[t].y;
    }
    __syncthreads();

    // down: thread owns 4 output cols (4*tid .. 4*tid+3) for all 16 tokens
    float4 acc[16];
    #pragma unroll
    for (int t = 0; t < 16; t++) acc[t] = make_float4(0.f, 0.f, 0.f, 0.f);
    const float* Wde = Wd + (size_t)e * NI * HH;
    #pragma unroll 4
    for (int i = 0; i < NI; i++) {
        float4 wd = *(const float4*)(Wde + (size_t)i * HH + tid * 4);
        #pragma unroll
        for (int t = 0; t < 16; t++) {
            float gv = Gs[t][i];
            acc[t].x += gv * wd.x; acc[t].y += gv * wd.y;
            acc[t].z += gv * wd.z; acc[t].w += gv * wd.w;
        }
    }
    #pragma unroll
    for (int t = 0; t < 16; t++) {
        int tk = toks[t];
        if (tk < 0) continue;
        float s = scs[t];
        float* op = out + (size_t)tk * HH + tid * 4;
        atomicAdd(op + 0, s * acc[t].x);
        atomicAdd(op + 1, s * acc[t].y);
        atomicAdd(op + 2, s * acc[t].z);
        atomicAdd(op + 3, s * acc[t].w);
    }
}

// ---------------- launch ----------------
extern "C" void kernel_launch(void* const* d_in, const int* in_sizes, int n_in,
                              void* d_out, int out_size) {
    const float* x    = (const float*)d_in[0];
    const float* cosp = (const float*)d_in[1];
    const float* sinp = (const float*)d_in[2];
    const float* ln1w = (const float*)d_in[3];
    const float* ln2w = (const float*)d_in[4];
    const float* Wq   = (const float*)d_in[5];
    const float* Wk   = (const float*)d_in[6];
    const float* Wv   = (const float*)d_in[7];
    const float* Wo   = (const float*)d_in[8];
    const float* Wr   = (const float*)d_in[9];
    const float* Wg   = (const float*)d_in[10];
    const float* Wu   = (const float*)d_in[11];
    const float* Wd   = (const float*)d_in[12];

    float* out    = (float*)d_out;                       // [NTOK, HH]
    float* logits = (float*)d_out + (size_t)NTOK * HH;   // [NTOK, NE]

    float *hb, *qb, *kb, *vb, *ab, *fb;
    cudaGetSymbolAddress((void**)&hb, g_h);
    cudaGetSymbolAddress((void**)&qb, g_q);
    cudaGetSymbolAddress((void**)&kb, g_k);
    cudaGetSymbolAddress((void**)&vb, g_v);
    cudaGetSymbolAddress((void**)&ab, g_att);
    cudaGetSymbolAddress((void**)&fb, g_f);

    // 1. rmsnorm1
    rmsnorm_k<<<NTOK, 256>>>(x, ln1w, hb);
    // 2-4. QKV projections
    sgemm_k<<<dim3(NHD * HDD / 64, NTOK / 64), 256>>>(hb, Wq, nullptr, qb, NTOK, NHD * HDD, HH);
    sgemm_k<<<dim3(NKVH * HDD / 64, NTOK / 64), 256>>>(hb, Wk, nullptr, kb, NTOK, NKVH * HDD, HH);
    sgemm_k<<<dim3(NKVH * HDD / 64, NTOK / 64), 256>>>(hb, Wv, nullptr, vb, NTOK, NKVH * HDD, HH);
    // 5. RoPE
    {
        int tq = NTOK * NHD * 32;
        rope_k<<<(tq + 255) / 256, 256>>>(qb, cosp, sinp, NHD, tq);
        int tk = NTOK * NKVH * 32;
        rope_k<<<(tk + 255) / 256, 256>>>(kb, cosp, sinp, NKVH, tk);
    }
    // 6. attention
    attn_k<<<dim3(TT / 128, BB * NHD), 128>>>(qb, kb, vb, ab);
    // 7. Wo + residual -> out (x2 lives in d_out)
    sgemm_k<<<dim3(HH / 64, NTOK / 64), 256>>>(ab, Wo, x, out, NTOK, HH, HH);
    // 8. rmsnorm2
    rmsnorm_k<<<NTOK, 256>>>(out, ln2w, fb);
    // 9. router logits -> second output region
    sgemm_k<<<dim3(NE / 64, NTOK / 64), 256>>>(fb, Wr, nullptr, logits, NTOK, NE, HH);
    // 10-11. top-8 + scatter
    zero_cnt_k<<<1, 64>>>();
    topk_k<<<(NTOK + 255) / 256, 256>>>(logits);
    // 12. MoE (adds into out)
    moe_k<<<dim3(NE, NTOK / 16), 256>>>(fb, Wg, Wu, Wd, out);
}